// round 8
// baseline (speedup 1.0000x reference)
#include <cuda_runtime.h>
#include <cuda_bf16.h>

// RandomPrompter: out[b,c,h,w] = x[b,c,h,w] + (patch inside per-sample 30x30 window)
// Shapes: x [256,3,224,224] f32, patch [1,3,30,30] f32, offsets [256,2] i32.
//
// Streaming op pinned at the DRAM wall (~7.4 TB/s effective, 92.6% of spec).
// This round: persistent grid-stride kernel with a software-pipelined loop —
// next iteration's load is issued before the current iteration's store, so
// per-thread MLP>=2 is sustained across the whole kernel instead of bursting
// once per short-lived CTA.

#define BATCH 256
#define CH    3
#define HH    224
#define WW    224
#define PSZ   30

#define W4        (WW / 4)                        // 56 float4 per row
#define TOTAL_V4  (BATCH * CH * HH * W4)          // 9,633,792 float4s
#define TPB       256
#define NCTA      (148 * 8)                       // 1184 persistent CTAs

__device__ __forceinline__ void patch_add(float4& val, int v,
                                          const float* __restrict__ patch,
                                          const int2* __restrict__ offsets)
{
    // v = ((b*3 + c)*224 + h)*56 + w4
    int w4 = v % W4;
    int t  = v / W4;
    int h  = t % HH;
    int t2 = t / HH;
    int c  = t2 % CH;
    int b  = t2 / CH;

    int2 off = __ldg(&offsets[b]);   // (row, col), each in [0, 194)
    int dh = h - off.x;
    if ((unsigned)dh < (unsigned)PSZ) {
        const float* prow = patch + (c * PSZ + dh) * PSZ;
        int dw = w4 * 4 - off.y;     // patch-relative column of lane 0
        if ((unsigned)(dw + 0) < (unsigned)PSZ) val.x += __ldg(&prow[dw + 0]);
        if ((unsigned)(dw + 1) < (unsigned)PSZ) val.y += __ldg(&prow[dw + 1]);
        if ((unsigned)(dw + 2) < (unsigned)PSZ) val.z += __ldg(&prow[dw + 2]);
        if ((unsigned)(dw + 3) < (unsigned)PSZ) val.w += __ldg(&prow[dw + 3]);
    }
}

__global__ __launch_bounds__(TPB) void random_prompter_kernel(
    const float4* __restrict__ x,
    const float* __restrict__ patch,
    const int2* __restrict__ offsets,
    float4* __restrict__ out)
{
    const int stride = NCTA * TPB;                 // 303,104
    int v = blockIdx.x * TPB + threadIdx.x;

    if (v >= TOTAL_V4) return;                     // (never taken; stride < total)

    // Software pipeline: cur in flight, issue next before storing cur.
    float4 cur = __ldcs(&x[v]);

    int vn = v + stride;
    while (vn < TOTAL_V4) {
        float4 nxt = __ldcs(&x[vn]);               // overlap with cur's patch+store
        patch_add(cur, v, patch, offsets);
        __stcs(&out[v], cur);
        cur = nxt;
        v = vn;
        vn += stride;
    }

    patch_add(cur, v, patch, offsets);
    __stcs(&out[v], cur);
}

extern "C" void kernel_launch(void* const* d_in, const int* in_sizes, int n_in,
                              void* d_out, int out_size)
{
    const float4* x      = (const float4*)d_in[0];
    const float*  patch  = (const float*)d_in[1];
    const int2*   offs   = (const int2*)d_in[2];
    float4*       out    = (float4*)d_out;

    random_prompter_kernel<<<NCTA, TPB>>>(x, patch, offs, out);
}

// round 9
// speedup vs baseline: 1.0832x; 1.0832x over previous
#include <cuda_runtime.h>
#include <cuda_bf16.h>

// RandomPrompter: out[b,c,h,w] = x[b,c,h,w] + (patch inside per-sample 30x30 window)
// Shapes: x [256,3,224,224] f32, patch [1,3,30,30] f32, offsets [256,2] i32.
//
// TERMINAL KERNEL. Pure streaming op (308 MB, zero reuse) pinned at the DRAM
// read/write-mix wall. Search matrix covered: {float4, v8(256-bit)} x
// {MLP 1,2,4} x {TPB 128,256,512} x {ldcs,ldcg} x {one-shot, persistent
// pipelined}. Best: one-shot float4 x MLP=2, TPB=256, evict-first (.cs).
// 308 MB / 41.6us = 7.4 TB/s effective = ~93% of 8 TB/s HBM spec.
// (Persistent loop regressed: dependency-chained loads < independent warps.)

#define BATCH 256
#define CH    3
#define HH    224
#define WW    224
#define PSZ   30

#define W4        (WW / 4)                        // 56 float4 per row
#define TOTAL_V4  (BATCH * CH * HH * W4)          // 9,633,792 float4s
#define VPT       2                               // float4s per thread
#define TPB       256
#define TILE      (TPB * VPT)                     // 512 float4s per block

__device__ __forceinline__ void patch_add(float4& val, int v,
                                          const float* __restrict__ patch,
                                          const int2* __restrict__ offsets)
{
    // v = ((b*3 + c)*224 + h)*56 + w4
    int w4 = v % W4;
    int t  = v / W4;
    int h  = t % HH;
    int t2 = t / HH;
    int c  = t2 % CH;
    int b  = t2 / CH;

    int2 off = __ldg(&offsets[b]);   // (row, col), each in [0, 194)
    int dh = h - off.x;
    if ((unsigned)dh < (unsigned)PSZ) {
        const float* prow = patch + (c * PSZ + dh) * PSZ;
        int dw = w4 * 4 - off.y;     // patch-relative column of lane 0
        if ((unsigned)(dw + 0) < (unsigned)PSZ) val.x += __ldg(&prow[dw + 0]);
        if ((unsigned)(dw + 1) < (unsigned)PSZ) val.y += __ldg(&prow[dw + 1]);
        if ((unsigned)(dw + 2) < (unsigned)PSZ) val.z += __ldg(&prow[dw + 2]);
        if ((unsigned)(dw + 3) < (unsigned)PSZ) val.w += __ldg(&prow[dw + 3]);
    }
}

__global__ __launch_bounds__(TPB) void random_prompter_kernel(
    const float4* __restrict__ x,
    const float* __restrict__ patch,
    const int2* __restrict__ offsets,
    float4* __restrict__ out)
{
    int base = blockIdx.x * TILE + threadIdx.x;
    int v0 = base;
    int v1 = base + TPB;

    // TOTAL_V4 (9,633,792) is divisible by TILE (512): 18816 blocks, no tail.
    // Both loads issued before either consumes (MLP=2 per thread).
    float4 a = __ldcs(&x[v0]);
    float4 b = __ldcs(&x[v1]);

    patch_add(a, v0, patch, offsets);
    patch_add(b, v1, patch, offsets);

    __stcs(&out[v0], a);
    __stcs(&out[v1], b);
}

extern "C" void kernel_launch(void* const* d_in, const int* in_sizes, int n_in,
                              void* d_out, int out_size)
{
    const float4* x      = (const float4*)d_in[0];
    const float*  patch  = (const float*)d_in[1];
    const int2*   offs   = (const int2*)d_in[2];
    float4*       out    = (float4*)d_out;

    const int blocks = TOTAL_V4 / TILE;  // 18816, exact
    random_prompter_kernel<<<blocks, TPB>>>(x, patch, offs, out);
}